// round 15
// baseline (speedup 1.0000x reference)
#include <cuda_runtime.h>
#include <cuda_bf16.h>
#include <cstdint>
#include <cstddef>

// ---------------------------------------------------------------------------
// SAGE 3-layer GraphSAGE. R15 = R14 (656us) + gather0/gemm0 stream overlap:
//   gather0 split into M-halves; gemm0-A (rows [0,N1/2)) runs on side stream
//   concurrent with gather0-B. Unified predicated 4-batch gather0 loop.
// ---------------------------------------------------------------------------

namespace {
constexpr int kN1 = 262144, kN2 = 32768, kN3 = 8192;
constexpr int kE0 = 1310720, kE1 = 327680, kE2 = 81920;
constexpr int kF = 100, kH = 256, kC = 47;
constexpr int kNT = kN1 + kN2 + kN3;
constexpr int kET = kE0 + kE1 + kE2;
constexpr int kHalf = kN1 / 2;
}  // namespace

__device__ float g_h1[(size_t)kN1 * kH];
__device__ float g_h2[(size_t)kN2 * kH];

__device__ int g_ints[2 * kNT + 3];
__device__ int g_off[kNT];
__device__ int g_csc[kET];

__device__ __nv_bfloat16 g_xs_hi[(size_t)kN1 * 128], g_xs_lo[(size_t)kN1 * 128];
__device__ __nv_bfloat16 g_a0_hi[(size_t)kN1 * 128], g_a0_lo[(size_t)kN1 * 128];
__device__ __nv_bfloat16 g_h1s_hi[(size_t)kN2 * 256], g_h1s_lo[(size_t)kN2 * 256];
__device__ __nv_bfloat16 g_a1_hi[(size_t)kN2 * 256], g_a1_lo[(size_t)kN2 * 256];
__device__ __nv_bfloat16 g_h2s_hi[(size_t)kN3 * 256], g_h2s_lo[(size_t)kN3 * 256];
__device__ __nv_bfloat16 g_a2_hi[(size_t)kN3 * 256], g_a2_lo[(size_t)kN3 * 256];

__device__ __nv_bfloat16 g_w0_hi[2 * 128 * 256], g_w0_lo[2 * 128 * 256];
__device__ __nv_bfloat16 g_w1_hi[2 * 256 * 256], g_w1_lo[2 * 256 * 256];
__device__ __nv_bfloat16 g_w2_hi[2 * 256 * 128], g_w2_lo[2 * 256 * 128];

// ======================== PTX helpers =========================================
__device__ __forceinline__ uint32_t smem_u32(const void* p) {
    return (uint32_t)__cvta_generic_to_shared(p);
}
__device__ __forceinline__ void ldsm4(uint32_t* r, uint32_t addr) {
    asm volatile("ldmatrix.sync.aligned.m8n8.x4.shared.b16 {%0,%1,%2,%3}, [%4];"
                 : "=r"(r[0]), "=r"(r[1]), "=r"(r[2]), "=r"(r[3]) : "r"(addr));
}
__device__ __forceinline__ void ldsm4t(uint32_t* r, uint32_t addr) {
    asm volatile("ldmatrix.sync.aligned.m8n8.x4.trans.shared.b16 {%0,%1,%2,%3}, [%4];"
                 : "=r"(r[0]), "=r"(r[1]), "=r"(r[2]), "=r"(r[3]) : "r"(addr));
}
__device__ __forceinline__ void mma_bf16(float* d, const uint32_t* a,
                                         uint32_t b0, uint32_t b1) {
    asm volatile(
        "mma.sync.aligned.m16n8k16.row.col.f32.bf16.bf16.f32 "
        "{%0,%1,%2,%3}, {%4,%5,%6,%7}, {%8,%9}, {%0,%1,%2,%3};"
        : "+f"(d[0]), "+f"(d[1]), "+f"(d[2]), "+f"(d[3])
        : "r"(a[0]), "r"(a[1]), "r"(a[2]), "r"(a[3]), "r"(b0), "r"(b1));
}
__device__ __forceinline__ uint32_t cvt_bf16x2(float a, float b) {
    uint32_t r;
    asm("cvt.rn.bf16x2.f32 %0, %1, %2;" : "=r"(r) : "f"(b), "f"(a));
    return r;
}
__device__ __forceinline__ void cp_async16(uint32_t saddr, const void* gptr) {
    asm volatile("cp.async.ca.shared.global [%0], [%1], 16;"
                 :: "r"(saddr), "l"(gptr));
}
#define CP_COMMIT() asm volatile("cp.async.commit_group;" ::: "memory")

// ======================== fused CSC build =====================================
__global__ void zero_int(int* __restrict__ p, int n) {
    int i = blockIdx.x * blockDim.x + threadIdx.x;
    if (i < n) p[i] = 0;
}
__global__ void count3(const int* __restrict__ ed0, const int* __restrict__ ed1,
                       const int* __restrict__ ed2, int* __restrict__ cnt) {
    int i = blockIdx.x * blockDim.x + threadIdx.x;
    if (i < kE0) {
        atomicAdd(cnt + __ldg(ed0 + i), 1);
    } else if (i < kE0 + kE1) {
        atomicAdd(cnt + kN1 + __ldg(ed1 + (i - kE0)), 1);
    } else if (i < kET) {
        atomicAdd(cnt + kN1 + kN2 + __ldg(ed2 + (i - kE0 - kE1)), 1);
    }
}
__global__ void reserve3(const int* __restrict__ cnt, int* __restrict__ off,
                         int* __restrict__ cursor) {
    __shared__ int s[256];
    __shared__ int base;
    int b = blockIdx.x, tid = threadIdx.x;
    int seg;
    if (b < kN1 / 256)               seg = 0;
    else if (b < (kN1 + kN2) / 256)  seg = 1;
    else                             seg = 2;
    int i = b * 256 + tid;
    int v = __ldg(cnt + i);
    s[tid] = v;
    __syncthreads();
#pragma unroll
    for (int dd = 1; dd < 256; dd <<= 1) {
        int t = (tid >= dd) ? s[tid - dd] : 0;
        __syncthreads();
        s[tid] += t;
        __syncthreads();
    }
    if (tid == 255) base = atomicAdd(cursor + seg, s[255]);
    __syncthreads();
    off[i] = base + s[tid] - v;
}
__global__ void fill3(const int* __restrict__ es0, const int* __restrict__ ed0,
                      const int* __restrict__ es1, const int* __restrict__ ed1,
                      const int* __restrict__ es2, const int* __restrict__ ed2,
                      const int* __restrict__ off, int* __restrict__ cur,
                      int* __restrict__ csc) {
    int i = blockIdx.x * blockDim.x + threadIdx.x;
    if (i < kE0) {
        int d = __ldg(ed0 + i);
        int p = atomicAdd(cur + d, 1);
        csc[__ldg(off + d) + p] = __ldg(es0 + i);
    } else if (i < kE0 + kE1) {
        int j = i - kE0;
        int d = kN1 + __ldg(ed1 + j);
        int p = atomicAdd(cur + d, 1);
        csc[kE0 + __ldg(off + d) + p] = __ldg(es1 + j);
    } else if (i < kET) {
        int j = i - kE0 - kE1;
        int d = kN1 + kN2 + __ldg(ed2 + j);
        int p = atomicAdd(cur + d, 1);
        csc[kE0 + kE1 + __ldg(off + d) + p] = __ldg(es2 + j);
    }
}

// ======================== gather0: occupancy-tuned, predicated 4-batch ========
// One warp per dst; 128-thr blocks; launch_bounds(128,16). Processes dst rows
// [dBase, dBase+nd). All 4 loads per batch independent (predicated tail).
template <int K, int KPAD>
__global__ void __launch_bounds__(128, 16)
gather0_kern(const float* __restrict__ feat, const int* __restrict__ off,
             const int* __restrict__ cnt, const int* __restrict__ csc,
             int dBase, int nd, uint2* __restrict__ hi, uint2* __restrict__ lo) {
    constexpr int NV = K / 4;      // 25
    constexpr int PV = KPAD / 4;   // 32
    static_assert(NV <= 32, "single float4 column per lane");
    int d = dBase + ((blockIdx.x * blockDim.x + threadIdx.x) >> 5);
    int lane = threadIdx.x & 31;
    if (d >= dBase + nd) return;
    int o0 = __ldg(off + d);
    int deg = __ldg(cnt + d);
    const bool act = lane < NV;
    float4 acc = make_float4(0.f, 0.f, 0.f, 0.f);
    for (int e = 0; e < deg; e += 4) {
        int rem = deg - e;
        int s0 = __ldg(csc + o0 + e);
        int s1 = (rem > 1) ? __ldg(csc + o0 + e + 1) : 0;
        int s2 = (rem > 2) ? __ldg(csc + o0 + e + 2) : 0;
        int s3 = (rem > 3) ? __ldg(csc + o0 + e + 3) : 0;
        if (act) {
            float4 f0 = __ldg(reinterpret_cast<const float4*>(feat + (size_t)s0 * K) + lane);
            float4 f1 = make_float4(0.f, 0.f, 0.f, 0.f);
            float4 f2 = make_float4(0.f, 0.f, 0.f, 0.f);
            float4 f3 = make_float4(0.f, 0.f, 0.f, 0.f);
            if (rem > 1) f1 = __ldg(reinterpret_cast<const float4*>(feat + (size_t)s1 * K) + lane);
            if (rem > 2) f2 = __ldg(reinterpret_cast<const float4*>(feat + (size_t)s2 * K) + lane);
            if (rem > 3) f3 = __ldg(reinterpret_cast<const float4*>(feat + (size_t)s3 * K) + lane);
            acc.x += (f0.x + f1.x) + (f2.x + f3.x);
            acc.y += (f0.y + f1.y) + (f2.y + f3.y);
            acc.z += (f0.z + f1.z) + (f2.z + f3.z);
            acc.w += (f0.w + f1.w) + (f2.w + f3.w);
        }
    }
    if (!act) return;   // pad columns (lane >= NV) stay .bss zero forever
    float r = 1.f / fmaxf((float)deg, 1.f);
    float4 w;
    w.x = acc.x * r; w.y = acc.y * r; w.z = acc.z * r; w.w = acc.w * r;
    uint32_t hx = __float_as_uint(w.x) & 0xFFFF0000u;
    uint32_t hy = __float_as_uint(w.y) & 0xFFFF0000u;
    uint32_t hz = __float_as_uint(w.z) & 0xFFFF0000u;
    uint32_t hw = __float_as_uint(w.w) & 0xFFFF0000u;
    uint2 ho, lv;
    ho.x = (hx >> 16) | hy;
    ho.y = (hz >> 16) | hw;
    lv.x = cvt_bf16x2(w.x - __uint_as_float(hx), w.y - __uint_as_float(hy));
    lv.y = cvt_bf16x2(w.z - __uint_as_float(hz), w.w - __uint_as_float(hw));
    size_t oidx = (size_t)d * PV + lane;
    hi[oidx] = ho;
    lo[oidx] = lv;
}

// ======================== gather-mean + split (layers 1/2) ====================
template <int K, int KPAD>
__global__ void gather_split(const float* __restrict__ feat,
                             const int* __restrict__ off,
                             const int* __restrict__ cnt,
                             const int* __restrict__ csc, int ndst,
                             uint2* __restrict__ hi, uint2* __restrict__ lo) {
    constexpr int NV = K / 4;
    constexpr int PV = KPAD / 4;
    constexpr int PER = (PV + 31) / 32;
    int d = (blockIdx.x * blockDim.x + threadIdx.x) >> 5;
    int lane = threadIdx.x & 31;
    if (d >= ndst) return;
    int o0 = __ldg(off + d);
    int deg = __ldg(cnt + d);
    float4 acc[PER];
#pragma unroll
    for (int p = 0; p < PER; ++p) acc[p] = make_float4(0.f, 0.f, 0.f, 0.f);
    int e = 0;
    for (; e + 8 <= deg; e += 8) {
        const float4* rr[8];
#pragma unroll
        for (int u = 0; u < 8; ++u) {
            int s = __ldg(csc + o0 + e + u);
            rr[u] = reinterpret_cast<const float4*>(feat + (size_t)s * K);
        }
#pragma unroll
        for (int p = 0; p < PER; ++p) {
            int v = lane + 32 * p;
            if (v < NV) {
                float4 f[8];
#pragma unroll
                for (int u = 0; u < 8; ++u) f[u] = __ldg(rr[u] + v);
#pragma unroll
                for (int u = 0; u < 8; ++u) {
                    acc[p].x += f[u].x; acc[p].y += f[u].y;
                    acc[p].z += f[u].z; acc[p].w += f[u].w;
                }
            }
        }
    }
    for (; e + 4 <= deg; e += 4) {
        const float4* rr[4];
#pragma unroll
        for (int u = 0; u < 4; ++u) {
            int s = __ldg(csc + o0 + e + u);
            rr[u] = reinterpret_cast<const float4*>(feat + (size_t)s * K);
        }
#pragma unroll
        for (int p = 0; p < PER; ++p) {
            int v = lane + 32 * p;
            if (v < NV) {
                float4 f[4];
#pragma unroll
                for (int u = 0; u < 4; ++u) f[u] = __ldg(rr[u] + v);
#pragma unroll
                for (int u = 0; u < 4; ++u) {
                    acc[p].x += f[u].x; acc[p].y += f[u].y;
                    acc[p].z += f[u].z; acc[p].w += f[u].w;
                }
            }
        }
    }
    for (; e < deg; ++e) {
        int s = __ldg(csc + o0 + e);
        const float4* row = reinterpret_cast<const float4*>(feat + (size_t)s * K);
#pragma unroll
        for (int p = 0; p < PER; ++p) {
            int v = lane + 32 * p;
            if (v < NV) {
                float4 f = __ldg(row + v);
                acc[p].x += f.x; acc[p].y += f.y; acc[p].z += f.z; acc[p].w += f.w;
            }
        }
    }
    float r = 1.f / fmaxf((float)deg, 1.f);
#pragma unroll
    for (int p = 0; p < PER; ++p) {
        int v = lane + 32 * p;
        if (v >= NV) continue;
        float4 w;
        w.x = acc[p].x * r; w.y = acc[p].y * r;
        w.z = acc[p].z * r; w.w = acc[p].w * r;
        uint32_t hx = __float_as_uint(w.x) & 0xFFFF0000u;
        uint32_t hy = __float_as_uint(w.y) & 0xFFFF0000u;
        uint32_t hz = __float_as_uint(w.z) & 0xFFFF0000u;
        uint32_t hw = __float_as_uint(w.w) & 0xFFFF0000u;
        uint2 ho, lv;
        ho.x = (hx >> 16) | hy;
        ho.y = (hz >> 16) | hw;
        lv.x = cvt_bf16x2(w.x - __uint_as_float(hx), w.y - __uint_as_float(hy));
        lv.y = cvt_bf16x2(w.z - __uint_as_float(hz), w.w - __uint_as_float(hw));
        size_t oidx = (size_t)d * PV + v;
        hi[oidx] = ho;
        lo[oidx] = lv;
    }
}

// ======================== misc small kernels ==================================
template <int K, int KPAD>
__global__ void split_kern(const float* __restrict__ in, int rows,
                           uint2* __restrict__ hi, uint2* __restrict__ lo) {
    constexpr int PR = KPAD / 4;
    int idx = blockIdx.x * blockDim.x + threadIdx.x;
    if (idx >= rows * PR) return;
    int row = idx / PR, kq = idx % PR;
    int k4 = kq * 4;
    if (k4 >= K) return;
    float4 v = *reinterpret_cast<const float4*>(in + (size_t)row * K + k4);
    uint32_t hx = __float_as_uint(v.x) & 0xFFFF0000u;
    uint32_t hy = __float_as_uint(v.y) & 0xFFFF0000u;
    uint32_t hz = __float_as_uint(v.z) & 0xFFFF0000u;
    uint32_t hw = __float_as_uint(v.w) & 0xFFFF0000u;
    uint2 ho, lv;
    ho.x = (hx >> 16) | hy;
    ho.y = (hz >> 16) | hw;
    lv.x = cvt_bf16x2(v.x - __uint_as_float(hx), v.y - __uint_as_float(hy));
    lv.y = cvt_bf16x2(v.z - __uint_as_float(hz), v.w - __uint_as_float(hw));
    size_t o = (size_t)row * PR + kq;
    hi[o] = ho;
    lo[o] = lv;
}

template <int K1, int NCOLS, int KPAD, int NPAD>
__global__ void prep_w(const float* __restrict__ Ws, const float* __restrict__ Wn,
                       __nv_bfloat16* __restrict__ hi, __nv_bfloat16* __restrict__ lo) {
    int idx = blockIdx.x * blockDim.x + threadIdx.x;
    constexpr int TOT = 2 * KPAD * NPAD;
    if (idx >= TOT) return;
    int phase = idx / (KPAD * NPAD);
    int rem = idx % (KPAD * NPAD);
    int k = rem / NPAD, n = rem % NPAD;
    float v = 0.f;
    if (k < K1 && n < NCOLS) v = (phase ? Wn : Ws)[(size_t)k * NCOLS + n];
    uint32_t h = __float_as_uint(v) & 0xFFFF0000u;
    hi[idx] = __ushort_as_bfloat16((unsigned short)(h >> 16));
    lo[idx] = __float2bfloat16(v - __uint_as_float(h));
}

// ======================== 2-stage cp.async bf16x3 GEMM (R9 config + mBase) ====
template <int KPAD, int NCOLS, int NPAD, bool RELU, bool WSPLIT>
__global__ void __launch_bounds__(256, 2)
gemm_mma(const __nv_bfloat16* __restrict__ As_hi, const __nv_bfloat16* __restrict__ As_lo,
         const __nv_bfloat16* __restrict__ An_hi, const __nv_bfloat16* __restrict__ An_lo,
         const __nv_bfloat16* __restrict__ W_hi, const __nv_bfloat16* __restrict__ W_lo,
         const float* __restrict__ bias, float* __restrict__ out,
         uint32_t* __restrict__ sp_hi, uint32_t* __restrict__ sp_lo,
         int split_rows, int mBase) {
    constexpr int BM = 128;
    constexpr int BK = 32;
    constexpr int AST = 40;
    constexpr int BST = 136;
    constexpr int ABYTES = BM * AST * 2;
    constexpr int BBYTES = BK * BST * 2;
    constexpr int SSTRIDE = 2 * ABYTES + 2 * BBYTES;
    constexpr int CPP = KPAD / BK;
    constexpr int NCH = 2 * CPP;

    extern __shared__ char smem[];
    const uint32_t su = smem_u32(smem);

    const int tid = threadIdx.x;
    const int lane = tid & 31, wid = tid >> 5;
    const int wm = wid & 1, wn = wid >> 1;
    const int nBlock = blockIdx.x * 128, mBlock = mBase + blockIdx.y * BM;

    const int ar = tid >> 1;
    const int ab = (tid & 1) * 32;
    const int br = tid >> 4;
    const int bc = tid & 15;

    auto issue_chunk = [&](int c) {
        const int stage = c & 1;
        const int phase = c / CPP;
        const int k0 = (c % CPP) * BK;
        const __nv_bfloat16* Ahi = phase ? An_hi : As_hi;
        const __nv_bfloat16* Alo = phase ? An_lo : As_lo;
        const uint32_t sb = su + stage * SSTRIDE;
        {
            size_t g = (size_t)(mBlock + ar) * KPAD + k0 + ab / 2;
            uint32_t sa = sb + 2u * (uint32_t)(ar * AST) + (uint32_t)ab;
            cp_async16(sa, Ahi + g);
            cp_async16(sa + 16, Ahi + g + 8);
            cp_async16(sa + (uint32_t)ABYTES, Alo + g);
            cp_async16(sa + (uint32_t)ABYTES + 16, Alo + g + 8);
        }
        {
            const __nv_bfloat16* wb =
                W_hi + (size_t)phase * KPAD * NPAD + (size_t)k0 * NPAD + nBlock;
            const __nv_bfloat16* wl =
                W_lo + (size_t)phase * KPAD * NPAD + (size_t)k0 * NPAD + nBlock;
#pragma unroll
            for (int it = 0; it < 2; ++it) {
                int r = br + it * 16;
                size_t g = (size_t)r * NPAD + bc * 8;
                uint32_t sbb = sb + 2u * (uint32_t)ABYTES +
                               2u * (uint32_t)(r * BST + bc * 8);
                cp_async16(sbb, wb + g);
                cp_async16(sbb + (uint32_t)BBYTES, wl + g);
            }
        }
        CP_COMMIT();
    };

    float acc[4][4][4];
#pragma unroll
    for (int i = 0; i < 4; i++)
#pragma unroll
        for (int j = 0; j < 4; j++)
#pragma unroll
            for (int r = 0; r < 4; r++) acc[i][j][r] = 0.f;

    const int lr = lane & 15;
    const int lc = (lane >> 4) * 8;
    const uint32_t aOff = 2u * (uint32_t)((wm * 64 + lr) * AST + lc);
    const uint32_t bOff = 2u * (uint32_t)ABYTES + 2u * (uint32_t)(lr * BST + wn * 32 + lc);

    issue_chunk(0);
    for (int c = 0; c < NCH; ++c) {
        if (c + 1 < NCH) {
            issue_chunk(c + 1);
            asm volatile("cp.async.wait_group 1;" ::: "memory");
        } else {
            asm volatile("cp.async.wait_group 0;" ::: "memory");
        }
        __syncthreads();
        const uint32_t sb = su + (c & 1) * SSTRIDE;
        const uint32_t aHiBase = sb + aOff;
        const uint32_t bHiBase = sb + bOff;
#pragma unroll
        for (int k16 = 0; k16 < BK / 16; ++k16) {
            const uint32_t kk = k16 * 16;
            uint32_t ah[4][4], bh[2][4];
#pragma unroll
            for (int p = 0; p < 2; ++p)
                ldsm4t(bh[p], bHiBase + 2u * (kk * BST + p * 16));
#pragma unroll
            for (int mt = 0; mt < 4; ++mt)
                ldsm4(ah[mt], aHiBase + 2u * (mt * 16 * AST + kk));
#pragma unroll
            for (int mt = 0; mt < 4; ++mt)
#pragma unroll
                for (int nt = 0; nt < 4; ++nt)
                    mma_bf16(acc[mt][nt], ah[mt], bh[nt >> 1][(nt & 1) * 2],
                             bh[nt >> 1][(nt & 1) * 2 + 1]);
            {
                uint32_t bl[2][4];
#pragma unroll
                for (int p = 0; p < 2; ++p)
                    ldsm4t(bl[p], bHiBase + (uint32_t)BBYTES + 2u * (kk * BST + p * 16));
#pragma unroll
                for (int mt = 0; mt < 4; ++mt)
#pragma unroll
                    for (int nt = 0; nt < 4; ++nt)
                        mma_bf16(acc[mt][nt], ah[mt], bl[nt >> 1][(nt & 1) * 2],
                                 bl[nt >> 1][(nt & 1) * 2 + 1]);
            }
            {
                uint32_t al[4][4];
#pragma unroll
                for (int mt = 0; mt < 4; ++mt)
                    ldsm4(al[mt], aHiBase + (uint32_t)ABYTES + 2u * (mt * 16 * AST + kk));
#pragma unroll
                for (int mt = 0; mt < 4; ++mt)
#pragma unroll
                    for (int nt = 0; nt < 4; ++nt)
                        mma_bf16(acc[mt][nt], al[mt], bh[nt >> 1][(nt & 1) * 2],
                                 bh[nt >> 1][(nt & 1) * 2 + 1]);
            }
        }
        __syncthreads();
    }

#pragma unroll
    for (int mt = 0; mt < 4; ++mt) {
        const int gmA = mBlock + wm * 64 + mt * 16 + (lane >> 2);
#pragma unroll
        for (int half = 0; half < 2; ++half) {
            const int gm = gmA + half * 8;
            float* orow = out + (size_t)gm * NCOLS;
#pragma unroll
            for (int nt = 0; nt < 4; ++nt) {
                const int gn = nBlock + wn * 32 + nt * 8 + (lane & 3) * 2;
                float v0 = acc[mt][nt][half * 2 + 0];
                float v1 = acc[mt][nt][half * 2 + 1];
                if constexpr (NCOLS % 128 == 0) {
                    v0 += __ldg(bias + gn);
                    v1 += __ldg(bias + gn + 1);
                    if (RELU) { v0 = fmaxf(v0, 0.f); v1 = fmaxf(v1, 0.f); }
                    *reinterpret_cast<float2*>(orow + gn) = make_float2(v0, v1);
                    if (WSPLIT && gm < split_rows) {
                        uint32_t h0 = __float_as_uint(v0) & 0xFFFF0000u;
                        uint32_t h1 = __float_as_uint(v1) & 0xFFFF0000u;
                        size_t so = (size_t)gm * (NCOLS / 2) + (gn >> 1);
                        sp_hi[so] = (h0 >> 16) | h1;
                        sp_lo[so] = cvt_bf16x2(v0 - __uint_as_float(h0),
                                               v1 - __uint_as_float(h1));
                    }
                } else {
                    if (gn < NCOLS) {
                        float v = v0 + __ldg(bias + gn);
                        if (RELU) v = fmaxf(v, 0.f);
                        orow[gn] = v;
                    }
                    if (gn + 1 < NCOLS) {
                        float v = v1 + __ldg(bias + gn + 1);
                        if (RELU) v = fmaxf(v, 0.f);
                        orow[gn + 1] = v;
                    }
                }
            }
        }
    }
}

// ======================== host launcher ======================================
static inline int cdiv_host(long long a, long long b) { return (int)((a + b - 1) / b); }

extern "C" void kernel_launch(void* const* d_in, const int* in_sizes, int n_in,
                              void* d_out, int out_size) {
    (void)in_sizes; (void)n_in; (void)out_size;
    const float* x   = (const float*)d_in[0];
    const int* es0   = (const int*)d_in[1];
    const int* ed0   = (const int*)d_in[2];
    const int* es1   = (const int*)d_in[3];
    const int* ed1   = (const int*)d_in[4];
    const int* es2   = (const int*)d_in[5];
    const int* ed2   = (const int*)d_in[6];
    const float* Ws0 = (const float*)d_in[7];
    const float* Wn0 = (const float*)d_in[8];
    const float* b0  = (const float*)d_in[9];
    const float* Ws1 = (const float*)d_in[10];
    const float* Wn1 = (const float*)d_in[11];
    const float* b1  = (const float*)d_in[12];
    const float* Ws2 = (const float*)d_in[13];
    const float* Wn2 = (const float*)d_in[14];
    const float* b2  = (const float*)d_in[15];
    float* out = (float*)d_out;

    float *h1, *h2;
    cudaGetSymbolAddress((void**)&h1, g_h1);
    cudaGetSymbolAddress((void**)&h2, g_h2);
    int *ints, *off, *csc;
    cudaGetSymbolAddress((void**)&ints, g_ints);
    cudaGetSymbolAddress((void**)&off, g_off);
    cudaGetSymbolAddress((void**)&csc, g_csc);
    int* cnt = ints;
    int* cur = ints + kNT;
    int* cursor = ints + 2 * kNT;

    __nv_bfloat16 *xs_hi, *xs_lo, *a0_hi, *a0_lo, *h1s_hi, *h1s_lo;
    __nv_bfloat16 *a1_hi, *a1_lo, *h2s_hi, *h2s_lo, *a2_hi, *a2_lo;
    cudaGetSymbolAddress((void**)&xs_hi, g_xs_hi);
    cudaGetSymbolAddress((void**)&xs_lo, g_xs_lo);
    cudaGetSymbolAddress((void**)&a0_hi, g_a0_hi);
    cudaGetSymbolAddress((void**)&a0_lo, g_a0_lo);
    cudaGetSymbolAddress((void**)&h1s_hi, g_h1s_hi);
    cudaGetSymbolAddress((void**)&h1s_lo, g_h1s_lo);
    cudaGetSymbolAddress((void**)&a1_hi, g_a1_hi);
    cudaGetSymbolAddress((void**)&a1_lo, g_a1_lo);
    cudaGetSymbolAddress((void**)&h2s_hi, g_h2s_hi);
    cudaGetSymbolAddress((void**)&h2s_lo, g_h2s_lo);
    cudaGetSymbolAddress((void**)&a2_hi, g_a2_hi);
    cudaGetSymbolAddress((void**)&a2_lo, g_a2_lo);
    __nv_bfloat16 *w0h, *w0l, *w1h, *w1l, *w2h, *w2l;
    cudaGetSymbolAddress((void**)&w0h, g_w0_hi);
    cudaGetSymbolAddress((void**)&w0l, g_w0_lo);
    cudaGetSymbolAddress((void**)&w1h, g_w1_hi);
    cudaGetSymbolAddress((void**)&w1l, g_w1_lo);
    cudaGetSymbolAddress((void**)&w2h, g_w2_hi);
    cudaGetSymbolAddress((void**)&w2l, g_w2_lo);

    const int T = 256;
    constexpr int SMEM_SZ = 2 * (2 * 128 * 40 * 2 + 2 * 32 * 136 * 2);  // 75776

    cudaFuncSetAttribute(gemm_mma<128, 256, 256, true, true>,
                         cudaFuncAttributeMaxDynamicSharedMemorySize, SMEM_SZ);
    cudaFuncSetAttribute(gemm_mma<256, 256, 256, true, true>,
                         cudaFuncAttributeMaxDynamicSharedMemorySize, SMEM_SZ);
    cudaFuncSetAttribute(gemm_mma<256, 47, 128, false, false>,
                         cudaFuncAttributeMaxDynamicSharedMemorySize, SMEM_SZ);

    static cudaStream_t side = nullptr;
    static cudaEvent_t evFork = nullptr, evPrep = nullptr, evGA = nullptr,
                       evG0A = nullptr;
    if (!side) {
        cudaStreamCreateWithFlags(&side, cudaStreamNonBlocking);
        cudaEventCreateWithFlags(&evFork, cudaEventDisableTiming);
        cudaEventCreateWithFlags(&evPrep, cudaEventDisableTiming);
        cudaEventCreateWithFlags(&evGA, cudaEventDisableTiming);
        cudaEventCreateWithFlags(&evG0A, cudaEventDisableTiming);
    }

    // ---- fork: side stream does split_x + weight prep
    cudaEventRecord(evFork, 0);
    cudaStreamWaitEvent(side, evFork, 0);
    split_kern<100, 128><<<cdiv_host((long long)kN1 * 32, T), T, 0, side>>>(
        x, kN1, (uint2*)xs_hi, (uint2*)xs_lo);
    prep_w<100, 256, 128, 256><<<cdiv_host(2 * 128 * 256, T), T, 0, side>>>(
        Ws0, Wn0, w0h, w0l);
    prep_w<256, 256, 256, 256><<<cdiv_host(2 * 256 * 256, T), T, 0, side>>>(
        Ws1, Wn1, w1h, w1l);
    prep_w<256, 47, 256, 128><<<cdiv_host(2 * 256 * 128, T), T, 0, side>>>(
        Ws2, Wn2, w2h, w2l);
    cudaEventRecord(evPrep, side);

    // ---- main: fused CSC build for all 3 layers
    zero_int<<<cdiv_host(2 * kNT + 3, T), T>>>(ints, 2 * kNT + 3);
    count3<<<cdiv_host(kET, T), T>>>(ed0, ed1, ed2, cnt);
    reserve3<<<kNT / 256, 256>>>(cnt, off, cursor);
    fill3<<<cdiv_host(kET, T), T>>>(es0, ed0, es1, ed1, es2, ed2, off, cur, csc);

    // ---- gather0 half A (rows [0, kHalf)), then half B; gemm0-A overlaps B
    gather0_kern<100, 128><<<kHalf / 4, 128>>>(x, off, cnt, csc, 0, kHalf,
                                               (uint2*)a0_hi, (uint2*)a0_lo);
    cudaEventRecord(evGA, 0);
    gather0_kern<100, 128><<<kHalf / 4, 128>>>(x, off, cnt, csc, kHalf, kHalf,
                                               (uint2*)a0_hi, (uint2*)a0_lo);

    // side: gemm0-A on rows [0, kHalf) — concurrent with gather0 half B.
    cudaStreamWaitEvent(side, evGA, 0);   // a0 half A ready (xs/weights in-order)
    gemm_mma<128, 256, 256, true, true><<<dim3(2, kHalf / 128), T, SMEM_SZ, side>>>(
        xs_hi, xs_lo, a0_hi, a0_lo, w0h, w0l, b0, h1,
        (uint32_t*)h1s_hi, (uint32_t*)h1s_lo, kN2, 0);
    cudaEventRecord(evG0A, side);

    // main: gemm0-B on rows [kHalf, kN1) (needs xs/weights from side prep)
    cudaStreamWaitEvent(0, evPrep, 0);
    gemm_mma<128, 256, 256, true, true><<<dim3(2, kHalf / 128), T, SMEM_SZ>>>(
        xs_hi, xs_lo, a0_hi, a0_lo, w0h, w0l, b0, h1,
        (uint32_t*)h1s_hi, (uint32_t*)h1s_lo, kN2, kHalf);

    // h1 complete once gemm0-A (side) also done
    cudaStreamWaitEvent(0, evG0A, 0);

    // ---------------- layer 1
    gather_split<256, 256><<<kN2 / 8, T>>>(h1, off + kN1, cnt + kN1, csc + kE0,
                                           kN2, (uint2*)a1_hi, (uint2*)a1_lo);
    gemm_mma<256, 256, 256, true, true><<<dim3(2, kN2 / 128), T, SMEM_SZ>>>(
        h1s_hi, h1s_lo, a1_hi, a1_lo, w1h, w1l, b1, h2,
        (uint32_t*)h2s_hi, (uint32_t*)h2s_lo, kN3, 0);

    // ---------------- layer 2
    gather_split<256, 256><<<kN3 / 8, T>>>(h2, off + kN1 + kN2, cnt + kN1 + kN2,
                                           csc + kE0 + kE1, kN3,
                                           (uint2*)a2_hi, (uint2*)a2_lo);
    gemm_mma<256, 47, 128, false, false><<<dim3(1, kN3 / 128), T, SMEM_SZ>>>(
        h2s_hi, h2s_lo, a2_hi, a2_lo, w2h, w2l, b2, out,
        nullptr, nullptr, 0, 0);
}

// round 16
// speedup vs baseline: 1.0628x; 1.0628x over previous
#include <cuda_runtime.h>
#include <cuda_bf16.h>
#include <cstdint>
#include <cstddef>

// ---------------------------------------------------------------------------
// SAGE 3-layer GraphSAGE. R16 = R15 minus split_x: gemm0 converts the fp32 x
// self-operand in-kernel (LDG->split->STS in the A loader), removing 384 MB
// of DRAM traffic from the saturated gather0/gemm0 phase.
// ---------------------------------------------------------------------------

namespace {
constexpr int kN1 = 262144, kN2 = 32768, kN3 = 8192;
constexpr int kE0 = 1310720, kE1 = 327680, kE2 = 81920;
constexpr int kF = 100, kH = 256, kC = 47;
constexpr int kNT = kN1 + kN2 + kN3;
constexpr int kET = kE0 + kE1 + kE2;
constexpr int kHalf = kN1 / 2;
}  // namespace

__device__ float g_h1[(size_t)kN1 * kH];
__device__ float g_h2[(size_t)kN2 * kH];

__device__ int g_ints[2 * kNT + 3];
__device__ int g_off[kNT];
__device__ int g_csc[kET];

__device__ __nv_bfloat16 g_a0_hi[(size_t)kN1 * 128], g_a0_lo[(size_t)kN1 * 128];
__device__ __nv_bfloat16 g_h1s_hi[(size_t)kN2 * 256], g_h1s_lo[(size_t)kN2 * 256];
__device__ __nv_bfloat16 g_a1_hi[(size_t)kN2 * 256], g_a1_lo[(size_t)kN2 * 256];
__device__ __nv_bfloat16 g_h2s_hi[(size_t)kN3 * 256], g_h2s_lo[(size_t)kN3 * 256];
__device__ __nv_bfloat16 g_a2_hi[(size_t)kN3 * 256], g_a2_lo[(size_t)kN3 * 256];

__device__ __nv_bfloat16 g_w0_hi[2 * 128 * 256], g_w0_lo[2 * 128 * 256];
__device__ __nv_bfloat16 g_w1_hi[2 * 256 * 256], g_w1_lo[2 * 256 * 256];
__device__ __nv_bfloat16 g_w2_hi[2 * 256 * 128], g_w2_lo[2 * 256 * 128];

// ======================== PTX helpers =========================================
__device__ __forceinline__ uint32_t smem_u32(const void* p) {
    return (uint32_t)__cvta_generic_to_shared(p);
}
__device__ __forceinline__ void ldsm4(uint32_t* r, uint32_t addr) {
    asm volatile("ldmatrix.sync.aligned.m8n8.x4.shared.b16 {%0,%1,%2,%3}, [%4];"
                 : "=r"(r[0]), "=r"(r[1]), "=r"(r[2]), "=r"(r[3]) : "r"(addr));
}
__device__ __forceinline__ void ldsm4t(uint32_t* r, uint32_t addr) {
    asm volatile("ldmatrix.sync.aligned.m8n8.x4.trans.shared.b16 {%0,%1,%2,%3}, [%4];"
                 : "=r"(r[0]), "=r"(r[1]), "=r"(r[2]), "=r"(r[3]) : "r"(addr));
}
__device__ __forceinline__ void mma_bf16(float* d, const uint32_t* a,
                                         uint32_t b0, uint32_t b1) {
    asm volatile(
        "mma.sync.aligned.m16n8k16.row.col.f32.bf16.bf16.f32 "
        "{%0,%1,%2,%3}, {%4,%5,%6,%7}, {%8,%9}, {%0,%1,%2,%3};"
        : "+f"(d[0]), "+f"(d[1]), "+f"(d[2]), "+f"(d[3])
        : "r"(a[0]), "r"(a[1]), "r"(a[2]), "r"(a[3]), "r"(b0), "r"(b1));
}
__device__ __forceinline__ uint32_t cvt_bf16x2(float a, float b) {
    uint32_t r;
    asm("cvt.rn.bf16x2.f32 %0, %1, %2;" : "=r"(r) : "f"(b), "f"(a));
    return r;
}
__device__ __forceinline__ void cp_async16(uint32_t saddr, const void* gptr) {
    asm volatile("cp.async.ca.shared.global [%0], [%1], 16;"
                 :: "r"(saddr), "l"(gptr));
}
#define CP_COMMIT() asm volatile("cp.async.commit_group;" ::: "memory")

// ======================== fused CSC build =====================================
__global__ void zero_int(int* __restrict__ p, int n) {
    int i = blockIdx.x * blockDim.x + threadIdx.x;
    if (i < n) p[i] = 0;
}
__global__ void count3(const int* __restrict__ ed0, const int* __restrict__ ed1,
                       const int* __restrict__ ed2, int* __restrict__ cnt) {
    int i = blockIdx.x * blockDim.x + threadIdx.x;
    if (i < kE0) {
        atomicAdd(cnt + __ldg(ed0 + i), 1);
    } else if (i < kE0 + kE1) {
        atomicAdd(cnt + kN1 + __ldg(ed1 + (i - kE0)), 1);
    } else if (i < kET) {
        atomicAdd(cnt + kN1 + kN2 + __ldg(ed2 + (i - kE0 - kE1)), 1);
    }
}
__global__ void reserve3(const int* __restrict__ cnt, int* __restrict__ off,
                         int* __restrict__ cursor) {
    __shared__ int s[256];
    __shared__ int base;
    int b = blockIdx.x, tid = threadIdx.x;
    int seg;
    if (b < kN1 / 256)               seg = 0;
    else if (b < (kN1 + kN2) / 256)  seg = 1;
    else                             seg = 2;
    int i = b * 256 + tid;
    int v = __ldg(cnt + i);
    s[tid] = v;
    __syncthreads();
#pragma unroll
    for (int dd = 1; dd < 256; dd <<= 1) {
        int t = (tid >= dd) ? s[tid - dd] : 0;
        __syncthreads();
        s[tid] += t;
        __syncthreads();
    }
    if (tid == 255) base = atomicAdd(cursor + seg, s[255]);
    __syncthreads();
    off[i] = base + s[tid] - v;
}
__global__ void fill3(const int* __restrict__ es0, const int* __restrict__ ed0,
                      const int* __restrict__ es1, const int* __restrict__ ed1,
                      const int* __restrict__ es2, const int* __restrict__ ed2,
                      const int* __restrict__ off, int* __restrict__ cur,
                      int* __restrict__ csc) {
    int i = blockIdx.x * blockDim.x + threadIdx.x;
    if (i < kE0) {
        int d = __ldg(ed0 + i);
        int p = atomicAdd(cur + d, 1);
        csc[__ldg(off + d) + p] = __ldg(es0 + i);
    } else if (i < kE0 + kE1) {
        int j = i - kE0;
        int d = kN1 + __ldg(ed1 + j);
        int p = atomicAdd(cur + d, 1);
        csc[kE0 + __ldg(off + d) + p] = __ldg(es1 + j);
    } else if (i < kET) {
        int j = i - kE0 - kE1;
        int d = kN1 + kN2 + __ldg(ed2 + j);
        int p = atomicAdd(cur + d, 1);
        csc[kE0 + kE1 + __ldg(off + d) + p] = __ldg(es2 + j);
    }
}

// ======================== gather0: occupancy-tuned, predicated 4-batch ========
template <int K, int KPAD>
__global__ void __launch_bounds__(128, 16)
gather0_kern(const float* __restrict__ feat, const int* __restrict__ off,
             const int* __restrict__ cnt, const int* __restrict__ csc,
             int dBase, int nd, uint2* __restrict__ hi, uint2* __restrict__ lo) {
    constexpr int NV = K / 4;      // 25
    constexpr int PV = KPAD / 4;   // 32
    static_assert(NV <= 32, "single float4 column per lane");
    int d = dBase + ((blockIdx.x * blockDim.x + threadIdx.x) >> 5);
    int lane = threadIdx.x & 31;
    if (d >= dBase + nd) return;
    int o0 = __ldg(off + d);
    int deg = __ldg(cnt + d);
    const bool act = lane < NV;
    float4 acc = make_float4(0.f, 0.f, 0.f, 0.f);
    for (int e = 0; e < deg; e += 4) {
        int rem = deg - e;
        int s0 = __ldg(csc + o0 + e);
        int s1 = (rem > 1) ? __ldg(csc + o0 + e + 1) : 0;
        int s2 = (rem > 2) ? __ldg(csc + o0 + e + 2) : 0;
        int s3 = (rem > 3) ? __ldg(csc + o0 + e + 3) : 0;
        if (act) {
            float4 f0 = __ldg(reinterpret_cast<const float4*>(feat + (size_t)s0 * K) + lane);
            float4 f1 = make_float4(0.f, 0.f, 0.f, 0.f);
            float4 f2 = make_float4(0.f, 0.f, 0.f, 0.f);
            float4 f3 = make_float4(0.f, 0.f, 0.f, 0.f);
            if (rem > 1) f1 = __ldg(reinterpret_cast<const float4*>(feat + (size_t)s1 * K) + lane);
            if (rem > 2) f2 = __ldg(reinterpret_cast<const float4*>(feat + (size_t)s2 * K) + lane);
            if (rem > 3) f3 = __ldg(reinterpret_cast<const float4*>(feat + (size_t)s3 * K) + lane);
            acc.x += (f0.x + f1.x) + (f2.x + f3.x);
            acc.y += (f0.y + f1.y) + (f2.y + f3.y);
            acc.z += (f0.z + f1.z) + (f2.z + f3.z);
            acc.w += (f0.w + f1.w) + (f2.w + f3.w);
        }
    }
    if (!act) return;
    float r = 1.f / fmaxf((float)deg, 1.f);
    float4 w;
    w.x = acc.x * r; w.y = acc.y * r; w.z = acc.z * r; w.w = acc.w * r;
    uint32_t hx = __float_as_uint(w.x) & 0xFFFF0000u;
    uint32_t hy = __float_as_uint(w.y) & 0xFFFF0000u;
    uint32_t hz = __float_as_uint(w.z) & 0xFFFF0000u;
    uint32_t hw = __float_as_uint(w.w) & 0xFFFF0000u;
    uint2 ho, lv;
    ho.x = (hx >> 16) | hy;
    ho.y = (hz >> 16) | hw;
    lv.x = cvt_bf16x2(w.x - __uint_as_float(hx), w.y - __uint_as_float(hy));
    lv.y = cvt_bf16x2(w.z - __uint_as_float(hz), w.w - __uint_as_float(hw));
    size_t oidx = (size_t)d * PV + lane;
    hi[oidx] = ho;
    lo[oidx] = lv;
}

// ======================== gather-mean + split (layers 1/2) ====================
template <int K, int KPAD>
__global__ void gather_split(const float* __restrict__ feat,
                             const int* __restrict__ off,
                             const int* __restrict__ cnt,
                             const int* __restrict__ csc, int ndst,
                             uint2* __restrict__ hi, uint2* __restrict__ lo) {
    constexpr int NV = K / 4;
    constexpr int PV = KPAD / 4;
    constexpr int PER = (PV + 31) / 32;
    int d = (blockIdx.x * blockDim.x + threadIdx.x) >> 5;
    int lane = threadIdx.x & 31;
    if (d >= ndst) return;
    int o0 = __ldg(off + d);
    int deg = __ldg(cnt + d);
    float4 acc[PER];
#pragma unroll
    for (int p = 0; p < PER; ++p) acc[p] = make_float4(0.f, 0.f, 0.f, 0.f);
    int e = 0;
    for (; e + 8 <= deg; e += 8) {
        const float4* rr[8];
#pragma unroll
        for (int u = 0; u < 8; ++u) {
            int s = __ldg(csc + o0 + e + u);
            rr[u] = reinterpret_cast<const float4*>(feat + (size_t)s * K);
        }
#pragma unroll
        for (int p = 0; p < PER; ++p) {
            int v = lane + 32 * p;
            if (v < NV) {
                float4 f[8];
#pragma unroll
                for (int u = 0; u < 8; ++u) f[u] = __ldg(rr[u] + v);
#pragma unroll
                for (int u = 0; u < 8; ++u) {
                    acc[p].x += f[u].x; acc[p].y += f[u].y;
                    acc[p].z += f[u].z; acc[p].w += f[u].w;
                }
            }
        }
    }
    for (; e + 4 <= deg; e += 4) {
        const float4* rr[4];
#pragma unroll
        for (int u = 0; u < 4; ++u) {
            int s = __ldg(csc + o0 + e + u);
            rr[u] = reinterpret_cast<const float4*>(feat + (size_t)s * K);
        }
#pragma unroll
        for (int p = 0; p < PER; ++p) {
            int v = lane + 32 * p;
            if (v < NV) {
                float4 f[4];
#pragma unroll
                for (int u = 0; u < 4; ++u) f[u] = __ldg(rr[u] + v);
#pragma unroll
                for (int u = 0; u < 4; ++u) {
                    acc[p].x += f[u].x; acc[p].y += f[u].y;
                    acc[p].z += f[u].z; acc[p].w += f[u].w;
                }
            }
        }
    }
    for (; e < deg; ++e) {
        int s = __ldg(csc + o0 + e);
        const float4* row = reinterpret_cast<const float4*>(feat + (size_t)s * K);
#pragma unroll
        for (int p = 0; p < PER; ++p) {
            int v = lane + 32 * p;
            if (v < NV) {
                float4 f = __ldg(row + v);
                acc[p].x += f.x; acc[p].y += f.y; acc[p].z += f.z; acc[p].w += f.w;
            }
        }
    }
    float r = 1.f / fmaxf((float)deg, 1.f);
#pragma unroll
    for (int p = 0; p < PER; ++p) {
        int v = lane + 32 * p;
        if (v >= NV) continue;
        float4 w;
        w.x = acc[p].x * r; w.y = acc[p].y * r;
        w.z = acc[p].z * r; w.w = acc[p].w * r;
        uint32_t hx = __float_as_uint(w.x) & 0xFFFF0000u;
        uint32_t hy = __float_as_uint(w.y) & 0xFFFF0000u;
        uint32_t hz = __float_as_uint(w.z) & 0xFFFF0000u;
        uint32_t hw = __float_as_uint(w.w) & 0xFFFF0000u;
        uint2 ho, lv;
        ho.x = (hx >> 16) | hy;
        ho.y = (hz >> 16) | hw;
        lv.x = cvt_bf16x2(w.x - __uint_as_float(hx), w.y - __uint_as_float(hy));
        lv.y = cvt_bf16x2(w.z - __uint_as_float(hz), w.w - __uint_as_float(hw));
        size_t oidx = (size_t)d * PV + v;
        hi[oidx] = ho;
        lo[oidx] = lv;
    }
}

// ======================== misc small kernels ==================================
template <int K1, int NCOLS, int KPAD, int NPAD>
__global__ void prep_w(const float* __restrict__ Ws, const float* __restrict__ Wn,
                       __nv_bfloat16* __restrict__ hi, __nv_bfloat16* __restrict__ lo) {
    int idx = blockIdx.x * blockDim.x + threadIdx.x;
    constexpr int TOT = 2 * KPAD * NPAD;
    if (idx >= TOT) return;
    int phase = idx / (KPAD * NPAD);
    int rem = idx % (KPAD * NPAD);
    int k = rem / NPAD, n = rem % NPAD;
    float v = 0.f;
    if (k < K1 && n < NCOLS) v = (phase ? Wn : Ws)[(size_t)k * NCOLS + n];
    uint32_t h = __float_as_uint(v) & 0xFFFF0000u;
    hi[idx] = __ushort_as_bfloat16((unsigned short)(h >> 16));
    lo[idx] = __float2bfloat16(v - __uint_as_float(h));
}

// ======================== 2-stage cp.async bf16x3 GEMM ========================
// SELFF32: self phase loads fp32 A (ld = kF) and splits to bf16 in-kernel.
template <int KPAD, int NCOLS, int NPAD, bool RELU, bool WSPLIT, bool SELFF32>
__global__ void __launch_bounds__(256, 2)
gemm_mma(const float* __restrict__ Asf,
         const __nv_bfloat16* __restrict__ As_hi, const __nv_bfloat16* __restrict__ As_lo,
         const __nv_bfloat16* __restrict__ An_hi, const __nv_bfloat16* __restrict__ An_lo,
         const __nv_bfloat16* __restrict__ W_hi, const __nv_bfloat16* __restrict__ W_lo,
         const float* __restrict__ bias, float* __restrict__ out,
         uint32_t* __restrict__ sp_hi, uint32_t* __restrict__ sp_lo,
         int split_rows, int mBase) {
    constexpr int BM = 128;
    constexpr int BK = 32;
    constexpr int AST = 40;
    constexpr int BST = 136;
    constexpr int ABYTES = BM * AST * 2;
    constexpr int BBYTES = BK * BST * 2;
    constexpr int SSTRIDE = 2 * ABYTES + 2 * BBYTES;
    constexpr int CPP = KPAD / BK;
    constexpr int NCH = 2 * CPP;

    extern __shared__ char smem[];
    const uint32_t su = smem_u32(smem);

    const int tid = threadIdx.x;
    const int lane = tid & 31, wid = tid >> 5;
    const int wm = wid & 1, wn = wid >> 1;
    const int nBlock = blockIdx.x * 128, mBlock = mBase + blockIdx.y * BM;

    const int ar = tid >> 1;
    const int ab = (tid & 1) * 32;
    const int br = tid >> 4;
    const int bc = tid & 15;

    auto issue_chunk = [&](int c) {
        const int stage = c & 1;
        const int phase = c / CPP;
        const int k0 = (c % CPP) * BK;
        if (SELFF32 && phase == 0) {
            // ---- A self: fp32 x -> split -> STS (row = ar, 16 cols/thread)
            const int c0 = (tid & 1) * 16;
            const int gm = mBlock + ar;
            uint32_t hv[8], lv[8];
#pragma unroll
            for (int j = 0; j < 4; ++j) {
                int col = k0 + c0 + 4 * j;
                float4 v = make_float4(0.f, 0.f, 0.f, 0.f);
                if (col < kF)
                    v = *reinterpret_cast<const float4*>(Asf + (size_t)gm * kF + col);
                uint32_t hx = __float_as_uint(v.x) & 0xFFFF0000u;
                uint32_t hy = __float_as_uint(v.y) & 0xFFFF0000u;
                uint32_t hz = __float_as_uint(v.z) & 0xFFFF0000u;
                uint32_t h3 = __float_as_uint(v.w) & 0xFFFF0000u;
                hv[2 * j]     = (hx >> 16) | hy;
                hv[2 * j + 1] = (hz >> 16) | h3;
                lv[2 * j]     = cvt_bf16x2(v.x - __uint_as_float(hx),
                                           v.y - __uint_as_float(hy));
                lv[2 * j + 1] = cvt_bf16x2(v.z - __uint_as_float(hz),
                                           v.w - __uint_as_float(h3));
            }
            char* dst = smem + stage * SSTRIDE + 2 * (ar * AST + c0);
            *reinterpret_cast<uint4*>(dst)      = make_uint4(hv[0], hv[1], hv[2], hv[3]);
            *reinterpret_cast<uint4*>(dst + 16) = make_uint4(hv[4], hv[5], hv[6], hv[7]);
            char* dstl = dst + ABYTES;
            *reinterpret_cast<uint4*>(dstl)      = make_uint4(lv[0], lv[1], lv[2], lv[3]);
            *reinterpret_cast<uint4*>(dstl + 16) = make_uint4(lv[4], lv[5], lv[6], lv[7]);
        } else {
            const __nv_bfloat16* Ahi = phase ? An_hi : As_hi;
            const __nv_bfloat16* Alo = phase ? An_lo : As_lo;
            const uint32_t sb = su + stage * SSTRIDE;
            size_t g = (size_t)(mBlock + ar) * KPAD + k0 + ab / 2;
            uint32_t sa = sb + 2u * (uint32_t)(ar * AST) + (uint32_t)ab;
            cp_async16(sa, Ahi + g);
            cp_async16(sa + 16, Ahi + g + 8);
            cp_async16(sa + (uint32_t)ABYTES, Alo + g);
            cp_async16(sa + (uint32_t)ABYTES + 16, Alo + g + 8);
        }
        {
            const uint32_t sb = su + stage * SSTRIDE;
            const __nv_bfloat16* wb =
                W_hi + (size_t)phase * KPAD * NPAD + (size_t)k0 * NPAD + nBlock;
            const __nv_bfloat16* wl =
                W_lo + (size_t)phase * KPAD * NPAD + (size_t)k0 * NPAD + nBlock;
#pragma unroll
            for (int it = 0; it < 2; ++it) {
                int r = br + it * 16;
                size_t g = (size_t)r * NPAD + bc * 8;
                uint32_t sbb = sb + 2u * (uint32_t)ABYTES +
                               2u * (uint32_t)(r * BST + bc * 8);
                cp_async16(sbb, wb + g);
                cp_async16(sbb + (uint32_t)BBYTES, wl + g);
            }
        }
        CP_COMMIT();
    };

    float acc[4][4][4];
#pragma unroll
    for (int i = 0; i < 4; i++)
#pragma unroll
        for (int j = 0; j < 4; j++)
#pragma unroll
            for (int r = 0; r < 4; r++) acc[i][j][r] = 0.f;

    const int lr = lane & 15;
    const int lc = (lane >> 4) * 8;
    const uint32_t aOff = 2u * (uint32_t)((wm * 64 + lr) * AST + lc);
    const uint32_t bOff = 2u * (uint32_t)ABYTES + 2u * (uint32_t)(lr * BST + wn * 32 + lc);

    issue_chunk(0);
    for (int c = 0; c < NCH; ++c) {
        if (c + 1 < NCH) {
            issue_chunk(c + 1);
            asm volatile("cp.async.wait_group 1;" ::: "memory");
        } else {
            asm volatile("cp.async.wait_group 0;" ::: "memory");
        }
        __syncthreads();
        const uint32_t sb = su + (c & 1) * SSTRIDE;
        const uint32_t aHiBase = sb + aOff;
        const uint32_t bHiBase = sb + bOff;
#pragma unroll
        for (int k16 = 0; k16 < BK / 16; ++k16) {
            const uint32_t kk = k16 * 16;
            uint32_t ah[4][4], bh[2][4];
#pragma unroll
            for (int p = 0; p < 2; ++p)
                ldsm4t(bh[p], bHiBase + 2u * (kk * BST + p * 16));
#pragma unroll
            for (int mt = 0; mt < 4; ++mt)
                ldsm4(ah[mt], aHiBase + 2u * (mt * 16 * AST + kk));
#pragma unroll
            for (int mt = 0; mt < 4; ++mt)
#pragma unroll
                for (int nt = 0; nt < 4; ++nt)
                    mma_bf16(acc[mt][nt], ah[mt], bh[nt >> 1][(nt & 1) * 2],
                             bh[nt >> 1][(nt & 1) * 2 + 1]);
            {
                uint32_t bl[2][4];
#pragma unroll
                for (int p = 0; p < 2; ++p)
                    ldsm4t(bl[p], bHiBase + (uint32_t)BBYTES + 2u * (kk * BST + p * 16));
#pragma unroll
                for (int mt = 0; mt < 4; ++mt)
#pragma unroll
                    for (int nt = 0; nt < 4; ++nt)
                        mma_bf16(acc[mt][nt], ah[mt], bl[nt >> 1][(nt & 1) * 2],
                                 bl[nt >> 1][(nt & 1) * 2 + 1]);
            }
            {
                uint32_t al[4][4];
#pragma unroll
                for (int mt = 0; mt < 4; ++mt)
                    ldsm4(al[mt], aHiBase + (uint32_t)ABYTES + 2u * (mt * 16 * AST + kk));
#pragma unroll
                for (int mt = 0; mt < 4; ++mt)
#pragma unroll
                    for (int nt = 0; nt < 4; ++nt)
                        mma_bf16(acc[mt][nt], al[mt], bh[nt >> 1][(nt & 1) * 2],
                                 bh[nt >> 1][(nt & 1) * 2 + 1]);
            }
        }
        __syncthreads();
    }

#pragma unroll
    for (int mt = 0; mt < 4; ++mt) {
        const int gmA = mBlock + wm * 64 + mt * 16 + (lane >> 2);
#pragma unroll
        for (int half = 0; half < 2; ++half) {
            const int gm = gmA + half * 8;
            float* orow = out + (size_t)gm * NCOLS;
#pragma unroll
            for (int nt = 0; nt < 4; ++nt) {
                const int gn = nBlock + wn * 32 + nt * 8 + (lane & 3) * 2;
                float v0 = acc[mt][nt][half * 2 + 0];
                float v1 = acc[mt][nt][half * 2 + 1];
                if constexpr (NCOLS % 128 == 0) {
                    v0 += __ldg(bias + gn);
                    v1 += __ldg(bias + gn + 1);
                    if (RELU) { v0 = fmaxf(v0, 0.f); v1 = fmaxf(v1, 0.f); }
                    *reinterpret_cast<float2*>(orow + gn) = make_float2(v0, v1);
                    if (WSPLIT && gm < split_rows) {
                        uint32_t h0 = __float_as_uint(v0) & 0xFFFF0000u;
                        uint32_t h1 = __float_as_uint(v1) & 0xFFFF0000u;
                        size_t so = (size_t)gm * (NCOLS / 2) + (gn >> 1);
                        sp_hi[so] = (h0 >> 16) | h1;
                        sp_lo[so] = cvt_bf16x2(v0 - __uint_as_float(h0),
                                               v1 - __uint_as_float(h1));
                    }
                } else {
                    if (gn < NCOLS) {
                        float v = v0 + __ldg(bias + gn);
                        if (RELU) v = fmaxf(v, 0.f);
                        orow[gn] = v;
                    }
                    if (gn + 1 < NCOLS) {
                        float v = v1 + __ldg(bias + gn + 1);
                        if (RELU) v = fmaxf(v, 0.f);
                        orow[gn + 1] = v;
                    }
                }
            }
        }
    }
}

// ======================== host launcher ======================================
static inline int cdiv_host(long long a, long long b) { return (int)((a + b - 1) / b); }

extern "C" void kernel_launch(void* const* d_in, const int* in_sizes, int n_in,
                              void* d_out, int out_size) {
    (void)in_sizes; (void)n_in; (void)out_size;
    const float* x   = (const float*)d_in[0];
    const int* es0   = (const int*)d_in[1];
    const int* ed0   = (const int*)d_in[2];
    const int* es1   = (const int*)d_in[3];
    const int* ed1   = (const int*)d_in[4];
    const int* es2   = (const int*)d_in[5];
    const int* ed2   = (const int*)d_in[6];
    const float* Ws0 = (const float*)d_in[7];
    const float* Wn0 = (const float*)d_in[8];
    const float* b0  = (const float*)d_in[9];
    const float* Ws1 = (const float*)d_in[10];
    const float* Wn1 = (const float*)d_in[11];
    const float* b1  = (const float*)d_in[12];
    const float* Ws2 = (const float*)d_in[13];
    const float* Wn2 = (const float*)d_in[14];
    const float* b2  = (const float*)d_in[15];
    float* out = (float*)d_out;

    float *h1, *h2;
    cudaGetSymbolAddress((void**)&h1, g_h1);
    cudaGetSymbolAddress((void**)&h2, g_h2);
    int *ints, *off, *csc;
    cudaGetSymbolAddress((void**)&ints, g_ints);
    cudaGetSymbolAddress((void**)&off, g_off);
    cudaGetSymbolAddress((void**)&csc, g_csc);
    int* cnt = ints;
    int* cur = ints + kNT;
    int* cursor = ints + 2 * kNT;

    __nv_bfloat16 *a0_hi, *a0_lo, *h1s_hi, *h1s_lo;
    __nv_bfloat16 *a1_hi, *a1_lo, *h2s_hi, *h2s_lo, *a2_hi, *a2_lo;
    cudaGetSymbolAddress((void**)&a0_hi, g_a0_hi);
    cudaGetSymbolAddress((void**)&a0_lo, g_a0_lo);
    cudaGetSymbolAddress((void**)&h1s_hi, g_h1s_hi);
    cudaGetSymbolAddress((void**)&h1s_lo, g_h1s_lo);
    cudaGetSymbolAddress((void**)&a1_hi, g_a1_hi);
    cudaGetSymbolAddress((void**)&a1_lo, g_a1_lo);
    cudaGetSymbolAddress((void**)&h2s_hi, g_h2s_hi);
    cudaGetSymbolAddress((void**)&h2s_lo, g_h2s_lo);
    cudaGetSymbolAddress((void**)&a2_hi, g_a2_hi);
    cudaGetSymbolAddress((void**)&a2_lo, g_a2_lo);
    __nv_bfloat16 *w0h, *w0l, *w1h, *w1l, *w2h, *w2l;
    cudaGetSymbolAddress((void**)&w0h, g_w0_hi);
    cudaGetSymbolAddress((void**)&w0l, g_w0_lo);
    cudaGetSymbolAddress((void**)&w1h, g_w1_hi);
    cudaGetSymbolAddress((void**)&w1l, g_w1_lo);
    cudaGetSymbolAddress((void**)&w2h, g_w2_hi);
    cudaGetSymbolAddress((void**)&w2l, g_w2_lo);

    const int T = 256;
    constexpr int SMEM_SZ = 2 * (2 * 128 * 40 * 2 + 2 * 32 * 136 * 2);  // 75776

    cudaFuncSetAttribute(gemm_mma<128, 256, 256, true, true, true>,
                         cudaFuncAttributeMaxDynamicSharedMemorySize, SMEM_SZ);
    cudaFuncSetAttribute(gemm_mma<256, 256, 256, true, true, false>,
                         cudaFuncAttributeMaxDynamicSharedMemorySize, SMEM_SZ);
    cudaFuncSetAttribute(gemm_mma<256, 47, 128, false, false, false>,
                         cudaFuncAttributeMaxDynamicSharedMemorySize, SMEM_SZ);

    static cudaStream_t side = nullptr;
    static cudaEvent_t evFork = nullptr, evPrep = nullptr, evGA = nullptr,
                       evG0A = nullptr;
    if (!side) {
        cudaStreamCreateWithFlags(&side, cudaStreamNonBlocking);
        cudaEventCreateWithFlags(&evFork, cudaEventDisableTiming);
        cudaEventCreateWithFlags(&evPrep, cudaEventDisableTiming);
        cudaEventCreateWithFlags(&evGA, cudaEventDisableTiming);
        cudaEventCreateWithFlags(&evG0A, cudaEventDisableTiming);
    }

    // ---- fork: side stream does weight prep only (split_x eliminated)
    cudaEventRecord(evFork, 0);
    cudaStreamWaitEvent(side, evFork, 0);
    prep_w<100, 256, 128, 256><<<cdiv_host(2 * 128 * 256, T), T, 0, side>>>(
        Ws0, Wn0, w0h, w0l);
    prep_w<256, 256, 256, 256><<<cdiv_host(2 * 256 * 256, T), T, 0, side>>>(
        Ws1, Wn1, w1h, w1l);
    prep_w<256, 47, 256, 128><<<cdiv_host(2 * 256 * 128, T), T, 0, side>>>(
        Ws2, Wn2, w2h, w2l);
    cudaEventRecord(evPrep, side);

    // ---- main: fused CSC build for all 3 layers
    zero_int<<<cdiv_host(2 * kNT + 3, T), T>>>(ints, 2 * kNT + 3);
    count3<<<cdiv_host(kET, T), T>>>(ed0, ed1, ed2, cnt);
    reserve3<<<kNT / 256, 256>>>(cnt, off, cursor);
    fill3<<<cdiv_host(kET, T), T>>>(es0, ed0, es1, ed1, es2, ed2, off, cur, csc);

    // ---- gather0 half A, then half B; gemm0-A overlaps B
    gather0_kern<100, 128><<<kHalf / 4, 128>>>(x, off, cnt, csc, 0, kHalf,
                                               (uint2*)a0_hi, (uint2*)a0_lo);
    cudaEventRecord(evGA, 0);
    gather0_kern<100, 128><<<kHalf / 4, 128>>>(x, off, cnt, csc, kHalf, kHalf,
                                               (uint2*)a0_hi, (uint2*)a0_lo);

    // side: gemm0-A on rows [0, kHalf) — concurrent with gather0 half B
    cudaStreamWaitEvent(side, evGA, 0);
    gemm_mma<128, 256, 256, true, true, true><<<dim3(2, kHalf / 128), T, SMEM_SZ, side>>>(
        x, nullptr, nullptr, a0_hi, a0_lo, w0h, w0l, b0, h1,
        (uint32_t*)h1s_hi, (uint32_t*)h1s_lo, kN2, 0);
    cudaEventRecord(evG0A, side);

    // main: gemm0-B on rows [kHalf, kN1)
    cudaStreamWaitEvent(0, evPrep, 0);
    gemm_mma<128, 256, 256, true, true, true><<<dim3(2, kHalf / 128), T, SMEM_SZ>>>(
        x, nullptr, nullptr, a0_hi, a0_lo, w0h, w0l, b0, h1,
        (uint32_t*)h1s_hi, (uint32_t*)h1s_lo, kN2, kHalf);

    cudaStreamWaitEvent(0, evG0A, 0);

    // ---------------- layer 1
    gather_split<256, 256><<<kN2 / 8, T>>>(h1, off + kN1, cnt + kN1, csc + kE0,
                                           kN2, (uint2*)a1_hi, (uint2*)a1_lo);
    gemm_mma<256, 256, 256, true, true, false><<<dim3(2, kN2 / 128), T, SMEM_SZ>>>(
        nullptr, h1s_hi, h1s_lo, a1_hi, a1_lo, w1h, w1l, b1, h2,
        (uint32_t*)h2s_hi, (uint32_t*)h2s_lo, kN3, 0);

    // ---------------- layer 2
    gather_split<256, 256><<<kN3 / 8, T>>>(h2, off + kN1 + kN2, cnt + kN1 + kN2,
                                           csc + kE0 + kE1, kN3,
                                           (uint2*)a2_hi, (uint2*)a2_lo);
    gemm_mma<256, 47, 128, false, false, false><<<dim3(1, kN3 / 128), T, SMEM_SZ>>>(
        nullptr, h2s_hi, h2s_lo, a2_hi, a2_lo, w2h, w2l, b2, out,
        nullptr, nullptr, 0, 0);
}